// round 2
// baseline (speedup 1.0000x reference)
#include <cuda_runtime.h>
#include <math.h>

// ---------------------------------------------------------------------------
// Problem constants
// ---------------------------------------------------------------------------
namespace {
constexpr int B_   = 8;
constexpr int S_   = 512;
constexpr int D_   = 1024;
constexpr int H_   = 8;
constexpr int DP_  = 128;              // head dim
constexpr int BH_  = B_ * H_;          // 64
constexpr int MS_  = B_ * S_;          // 4096  (rows of x)
constexpr int NSEG_ = 96;              // 3 streams * B * 4 heads
constexpr int NR_  = NSEG_ * S_;       // 49152 RNN rows
constexpr int ROWS_ = BH_ * S_;        // 32768 (b,h,q) rows
constexpr int NOUT_ = MS_ * D_;        // 4194304 elements of `out`
constexpr float INV_SCALE = 0.08838834764831845f;  // 1/sqrt(128)
}

// ---------------------------------------------------------------------------
// Scratch (static device globals -- no runtime allocation allowed)
// ---------------------------------------------------------------------------
__device__ float g_q  [BH_ * S_ * DP_];
__device__ float g_k  [BH_ * S_ * DP_];
__device__ float g_v  [BH_ * S_ * DP_];
__device__ float g_ctx[BH_ * S_ * DP_];
__device__ float g_A  [NR_ * DP_];   // feats @ Wih_f^T + bih_f
__device__ float g_Bm [NR_ * DP_];   // feats @ Wih_b^T + bih_b
__device__ float g_H1f[NR_ * DP_];
__device__ float g_H1b[NR_ * DP_];
__device__ float g_Yf [NR_ * DP_];
__device__ float g_P  [ROWS_ * 65];  // qs . rel_emb[j]
__device__ float g_R  [ROWS_ * 65];  // bucketed attn sums
__device__ int   g_mask[MS_];
__device__ float g_attn_fb[(size_t)BH_ * S_ * S_];  // fallback if d_out lacks attn

// ---------------------------------------------------------------------------
// Tiled GEMM cores.  64x64 block tile, K-step 16, 256 threads, 4x4 per thread.
// gemm_tn:  C = A * B^T   (A: [M,K] rm, B: [N,K] rm)
// gemm_nn:  C = A * B     (A: [M,K] rm, B: [K,N] rm)
// Loaders return float4; storeC gets local (i,j) within the 64x64 tile.
// ---------------------------------------------------------------------------
template <class FA, class FB, class FC>
__device__ __forceinline__ void gemm_tn(int K, FA loadA, FB loadB, FC storeC) {
    __shared__ float As[16][68];
    __shared__ float Bs[16][68];
    float acc[4][4];
#pragma unroll
    for (int i = 0; i < 4; i++)
#pragma unroll
        for (int j = 0; j < 4; j++) acc[i][j] = 0.f;
    const int tid = threadIdx.x;
    const int lr  = tid >> 2;          // 0..63
    const int lc  = (tid & 3) << 2;    // 0,4,8,12
    const int ty  = tid >> 4;          // 0..15
    const int tx  = tid & 15;          // 0..15
    for (int k0 = 0; k0 < K; k0 += 16) {
        float4 a = loadA(lr, k0 + lc);
        float4 b = loadB(lr, k0 + lc);
        As[lc + 0][lr] = a.x; As[lc + 1][lr] = a.y; As[lc + 2][lr] = a.z; As[lc + 3][lr] = a.w;
        Bs[lc + 0][lr] = b.x; Bs[lc + 1][lr] = b.y; Bs[lc + 2][lr] = b.z; Bs[lc + 3][lr] = b.w;
        __syncthreads();
#pragma unroll
        for (int kk = 0; kk < 16; kk++) {
            float ar[4], br[4];
#pragma unroll
            for (int i = 0; i < 4; i++) { ar[i] = As[kk][ty * 4 + i]; br[i] = Bs[kk][tx * 4 + i]; }
#pragma unroll
            for (int i = 0; i < 4; i++)
#pragma unroll
                for (int j = 0; j < 4; j++) acc[i][j] = fmaf(ar[i], br[j], acc[i][j]);
        }
        __syncthreads();
    }
#pragma unroll
    for (int i = 0; i < 4; i++)
#pragma unroll
        for (int j = 0; j < 4; j++) storeC(ty * 4 + i, tx * 4 + j, acc[i][j]);
}

template <class FA, class FB, class FC>
__device__ __forceinline__ void gemm_nn(int K, FA loadA, FB loadB, FC storeC) {
    __shared__ float As[16][68];
    __shared__ float Bs[16][68];
    float acc[4][4];
#pragma unroll
    for (int i = 0; i < 4; i++)
#pragma unroll
        for (int j = 0; j < 4; j++) acc[i][j] = 0.f;
    const int tid = threadIdx.x;
    const int lr  = tid >> 2;          // A row 0..63
    const int lc  = (tid & 3) << 2;    // A col 0,4,8,12
    const int lrB = tid >> 4;          // B k-row 0..15
    const int lcB = (tid & 15) << 2;   // B col 0..60
    const int ty  = tid >> 4;
    const int tx  = tid & 15;
    for (int k0 = 0; k0 < K; k0 += 16) {
        float4 a = loadA(lr, k0 + lc);
        float4 b = loadB(k0 + lrB, lcB);
        As[lc + 0][lr] = a.x; As[lc + 1][lr] = a.y; As[lc + 2][lr] = a.z; As[lc + 3][lr] = a.w;
        Bs[lrB][lcB + 0] = b.x; Bs[lrB][lcB + 1] = b.y; Bs[lrB][lcB + 2] = b.z; Bs[lrB][lcB + 3] = b.w;
        __syncthreads();
#pragma unroll
        for (int kk = 0; kk < 16; kk++) {
            float ar[4], br[4];
#pragma unroll
            for (int i = 0; i < 4; i++) { ar[i] = As[kk][ty * 4 + i]; br[i] = Bs[kk][tx * 4 + i]; }
#pragma unroll
            for (int i = 0; i < 4; i++)
#pragma unroll
                for (int j = 0; j < 4; j++) acc[i][j] = fmaf(ar[i], br[j], acc[i][j]);
        }
        __syncthreads();
    }
#pragma unroll
    for (int i = 0; i < 4; i++)
#pragma unroll
        for (int j = 0; j < 4; j++) storeC(ty * 4 + i, tx * 4 + j, acc[i][j]);
}

// ---------------------------------------------------------------------------
// 0) Mask normalization: detect uint8 / int32 / float32 encoding of the bool
//    mask and write 0/1 ints to g_mask.  Single block, deterministic.
// ---------------------------------------------------------------------------
__global__ void mask_norm_kernel(const void* raw) {
    __shared__ int f_int, f_flt;
    const unsigned int* w = (const unsigned int*)raw;
    int t = threadIdx.x;  // 1024 threads
    if (t == 0) { f_int = 1; f_flt = 1; }
    __syncthreads();
    // Inspect the first 4096 bytes (safe under any candidate dtype).
    unsigned int x = w[t];
    if (x != 0u && x != 1u) f_int = 0;
    if (x != 0u && x != 0x3F800000u) f_flt = 0;
    __syncthreads();
    if (f_int) {
        for (int i = t; i < MS_; i += 1024) g_mask[i] = (int)w[i];
    } else if (f_flt) {
        const float* f = (const float*)raw;
        for (int i = t; i < MS_; i += 1024) g_mask[i] = (f[i] != 0.f);
    } else {
        const unsigned char* bts = (const unsigned char*)raw;
        for (int i = t; i < MS_; i += 1024) g_mask[i] = (bts[i] != 0);
    }
}

// ---------------------------------------------------------------------------
// 1) QKV projections: z=0/1/2 -> q/k/v.  Epilogue: +bias, mask-zero, scatter
//    to (B,H,S,DP) head-major layout.
// ---------------------------------------------------------------------------
__global__ void __launch_bounds__(256) qkv_kernel(
    const float* __restrict__ x,
    const float* __restrict__ Wq, const float* __restrict__ bq,
    const float* __restrict__ Wk, const float* __restrict__ bk,
    const float* __restrict__ Wv, const float* __restrict__ bv) {
    const int z = blockIdx.z;
    const float* W    = (z == 0) ? Wq : (z == 1) ? Wk : Wv;
    const float* bias = (z == 0) ? bq : (z == 1) ? bk : bv;
    float* out        = (z == 0) ? g_q : (z == 1) ? g_k : g_v;
    const int bm = blockIdx.y * 64, bn = blockIdx.x * 64;
    gemm_tn(D_,
        [&](int r, int k) { return *(const float4*)(x + (size_t)(bm + r) * D_ + k); },
        [&](int r, int k) { return *(const float4*)(W + (size_t)(bn + r) * D_ + k); },
        [&](int il, int jl, float v) {
            int m = bm + il, n = bn + jl;
            int b = m >> 9, s = m & 511;
            int h = n >> 7, d = n & 127;
            float val = g_mask[m] ? 0.f : (v + bias[n]);
            out[((size_t)((b * H_ + h) * S_ + s)) * DP_ + d] = val;
        });
}

// ---------------------------------------------------------------------------
// 2) RNN input GEMMs: z=0 -> g_A = feats@Wih_f^T + bih_f
//                     z=1 -> g_Bm = feats@Wih_b^T + bih_b
//    feats rows gathered from g_q/g_k/g_v heads 4..7.
// ---------------------------------------------------------------------------
__device__ __forceinline__ const float* feats_row(int rr) {
    int f = rr >> 14;             // stream: 0=q 1=k 2=v  (32*512 = 16384)
    int rem = rr & 16383;
    int bh4 = rem >> 9;           // b*4+hh
    int s   = rem & 511;
    int b = bh4 >> 2, hh = bh4 & 3;
    const float* src = (f == 0) ? g_q : (f == 1) ? g_k : g_v;
    return src + ((size_t)((b * H_ + 4 + hh) * S_ + s)) * DP_;
}

__global__ void __launch_bounds__(256) rnn_in_kernel(
    const float* __restrict__ Wih_f, const float* __restrict__ bih_f,
    const float* __restrict__ Wih_b, const float* __restrict__ bih_b) {
    const int z = blockIdx.z;
    const float* W    = z ? Wih_b : Wih_f;
    const float* bias = z ? bih_b : bih_f;
    float* dst        = z ? g_Bm : g_A;
    const int bm = blockIdx.y * 64, bn = blockIdx.x * 64;
    gemm_tn(DP_,
        [&](int r, int k) { return *(const float4*)(feats_row(bm + r) + k); },
        [&](int r, int k) { return *(const float4*)(W + (size_t)(bn + r) * DP_ + k); },
        [&](int il, int jl, float v) {
            int m = bm + il, n = bn + jl;
            dst[(size_t)m * DP_ + n] = v + bias[n];
        });
}

// ---------------------------------------------------------------------------
// 3) First RNN step (elementwise, shift comes for free):
//    H1f[r] = tanh( (s>0 ? A[r-1] : bih_f) + bhh_f )
//    H1b[r] = tanh( Bm[r] + bhh_b )
// ---------------------------------------------------------------------------
__global__ void rnn_h1_kernel(const float* __restrict__ bih_f,
                              const float* __restrict__ bhh_f,
                              const float* __restrict__ bhh_b) {
    int gid = blockIdx.x * blockDim.x + threadIdx.x;
    if (gid >= NR_ * DP_) return;
    int r = gid >> 7, d = gid & 127;
    int s = r & 511;
    float af = s ? g_A[gid - DP_] : bih_f[d];
    g_H1f[gid] = tanhf(af + bhh_f[d]);
    g_H1b[gid] = tanhf(g_Bm[gid] + bhh_b[d]);
}

// ---------------------------------------------------------------------------
// 4) Forward step 2:  Yf = tanh( A + H1f@Whh_f^T + bhh_f )
// ---------------------------------------------------------------------------
__global__ void __launch_bounds__(256) rnn_h2f_kernel(
    const float* __restrict__ Whh_f, const float* __restrict__ bhh_f) {
    const int bm = blockIdx.y * 64, bn = blockIdx.x * 64;
    gemm_tn(DP_,
        [&](int r, int k) { return *(const float4*)(g_H1f + (size_t)(bm + r) * DP_ + k); },
        [&](int r, int k) { return *(const float4*)(Whh_f + (size_t)(bn + r) * DP_ + k); },
        [&](int il, int jl, float v) {
            int m = bm + il, n = bn + jl;
            size_t idx = (size_t)m * DP_ + n;
            g_Yf[idx] = tanhf(v + g_A[idx] + bhh_f[n]);
        });
}

// ---------------------------------------------------------------------------
// 5) Backward step 2 + combine + scatter back into q/k/v heads 4..7:
//    y = Yf + tanh( (s>0 ? Bm[r-1] : bih_b) + H1b@Whh_b^T + bhh_b )
// ---------------------------------------------------------------------------
__global__ void __launch_bounds__(256) rnn_h2b_kernel(
    const float* __restrict__ Whh_b, const float* __restrict__ bih_b,
    const float* __restrict__ bhh_b) {
    const int bm = blockIdx.y * 64, bn = blockIdx.x * 64;
    gemm_tn(DP_,
        [&](int r, int k) { return *(const float4*)(g_H1b + (size_t)(bm + r) * DP_ + k); },
        [&](int r, int k) { return *(const float4*)(Whh_b + (size_t)(bn + r) * DP_ + k); },
        [&](int il, int jl, float v) {
            int m = bm + il, n = bn + jl;
            int s = m & 511;
            float shiftB = s ? g_Bm[(size_t)(m - 1) * DP_ + n] : bih_b[n];
            float y = g_Yf[(size_t)m * DP_ + n] + tanhf(v + shiftB + bhh_b[n]);
            int f = m >> 14, rem = m & 16383, bh4 = rem >> 9;
            int b = bh4 >> 2, hh = bh4 & 3;
            float* dst = (f == 0) ? g_q : (f == 1) ? g_k : g_v;
            dst[((size_t)((b * H_ + 4 + hh) * S_ + s)) * DP_ + n] = y;
        });
}

// ---------------------------------------------------------------------------
// 6) P[row,j] = (q[row] . rel_emb[j]) / SCALE    (row = bh*S + s, j in [0,65))
// ---------------------------------------------------------------------------
__global__ void p_kernel(const float* __restrict__ rel_emb) {
    int gid = blockIdx.x * blockDim.x + threadIdx.x;
    if (gid >= ROWS_ * 65) return;
    int row = gid / 65, j = gid - row * 65;
    const float* qr = g_q + (size_t)row * DP_;
    const float* er = rel_emb + (size_t)j * DP_;
    float s = 0.f;
#pragma unroll 8
    for (int d = 0; d < DP_; d++) s = fmaf(qr[d], er[d], s);
    g_P[gid] = s * INV_SCALE;
}

// ---------------------------------------------------------------------------
// 7) scores (pre-softmax) into the attn buffer:
//    s[q,k] = (q.k)/SCALE + P[q, clip(k-q)+32];  masked-k -> -1e18
// ---------------------------------------------------------------------------
__global__ void __launch_bounds__(256) scores_kernel(float* __restrict__ attn,
                                                     int attn_in_out) {
    float* ap = attn_in_out ? attn : g_attn_fb;
    const int z = blockIdx.z;              // bh
    const int b = z >> 3;
    const int bm = blockIdx.y * 64, bn = blockIdx.x * 64;
    const float* qb = g_q + (size_t)z * S_ * DP_;
    const float* kb = g_k + (size_t)z * S_ * DP_;
    gemm_tn(DP_,
        [&](int r, int k) { return *(const float4*)(qb + (size_t)(bm + r) * DP_ + k); },
        [&](int r, int k) { return *(const float4*)(kb + (size_t)(bn + r) * DP_ + k); },
        [&](int il, int jl, float v) {
            int qi = bm + il, ki = bn + jl;
            float val;
            if (g_mask[b * S_ + ki]) {
                val = -1e18f;
            } else {
                int off = ki - qi;
                off = off < -32 ? -32 : (off > 32 ? 32 : off);
                val = v * INV_SCALE + g_P[((size_t)z * S_ + qi) * 65 + off + 32];
            }
            ap[(size_t)z * S_ * S_ + (size_t)qi * S_ + ki] = val;
        });
}

// ---------------------------------------------------------------------------
// 8) Softmax per row + bucketed rel sums R.  One block (256 thr) per row.
// ---------------------------------------------------------------------------
__device__ __forceinline__ float blk_reduce(float v, float* red, bool is_max) {
#pragma unroll
    for (int o = 16; o > 0; o >>= 1) {
        float w = __shfl_xor_sync(0xffffffffu, v, o);
        v = is_max ? fmaxf(v, w) : (v + w);
    }
    int warp = threadIdx.x >> 5, lane = threadIdx.x & 31;
    if (lane == 0) red[warp] = v;
    __syncthreads();
    float r = red[0];
#pragma unroll
    for (int i = 1; i < 8; i++) r = is_max ? fmaxf(r, red[i]) : (r + red[i]);
    __syncthreads();
    return r;
}

__global__ void __launch_bounds__(256) softmax_kernel(float* __restrict__ attn,
                                                      int attn_in_out) {
    float* ap = attn_in_out ? attn : g_attn_fb;
    int row = blockIdx.x;                 // bh*S + q
    int q = row & 511;
    float* p = ap + (size_t)row * S_;
    __shared__ float sh[S_];
    __shared__ float red[8];
    int t = threadIdx.x;
    float v0 = p[t], v1 = p[t + 256];
    float mx = blk_reduce(fmaxf(v0, v1), red, true);
    float e0 = expf(v0 - mx), e1 = expf(v1 - mx);
    float sum = blk_reduce(e0 + e1, red, false);
    float inv = 1.f / sum;
    e0 *= inv; e1 *= inv;
    p[t] = e0; p[t + 256] = e1;
    sh[t] = e0; sh[t + 256] = e1;
    // bucket sums: j=0 <-> k <= q-32, j=64 <-> k >= q+32
    float r0 = 0.f, r64 = 0.f;
    if (t <= q - 32)        r0  += e0;
    if (t >= q + 32)        r64 += e0;
    if (t + 256 <= q - 32)  r0  += e1;
    if (t + 256 >= q + 32)  r64 += e1;
    r0  = blk_reduce(r0,  red, false);
    r64 = blk_reduce(r64, red, false);
    float* Rr = g_R + (size_t)row * 65;
    if (t == 0) { Rr[0] = r0; Rr[64] = r64; }
    if (t >= 1 && t <= 63) {
        int k = q + t - 32;
        Rr[t] = (k >= 0 && k < S_) ? sh[k] : 0.f;
    }
}

// ---------------------------------------------------------------------------
// 9) ctx = attn @ v  (NN GEMM, per bh)
// ---------------------------------------------------------------------------
__global__ void __launch_bounds__(256) ctx_kernel(const float* __restrict__ attn,
                                                  int attn_in_out) {
    const float* ap = attn_in_out ? attn : g_attn_fb;
    const int z = blockIdx.z;
    const int bm = blockIdx.y * 64, bn = blockIdx.x * 64;
    const float* Ab = ap + (size_t)z * S_ * S_;
    const float* Vb = g_v + (size_t)z * S_ * DP_;
    gemm_nn(S_,
        [&](int r, int k) { return *(const float4*)(Ab + (size_t)(bm + r) * S_ + k); },
        [&](int k, int n) { return *(const float4*)(Vb + (size_t)k * DP_ + bn + n); },
        [&](int il, int jl, float v) {
            g_ctx[(size_t)z * S_ * DP_ + (size_t)(bm + il) * DP_ + bn + jl] = v;
        });
}

// ---------------------------------------------------------------------------
// 10) ctx += R @ rel_emb   (K=65, tiny)
// ---------------------------------------------------------------------------
__global__ void ctx_rel_kernel(const float* __restrict__ rel_emb) {
    int gid = blockIdx.x * blockDim.x + threadIdx.x;
    if (gid >= ROWS_ * DP_) return;
    int row = gid >> 7, d = gid & 127;
    const float* Rr = g_R + (size_t)row * 65;
    float s = 0.f;
#pragma unroll
    for (int j = 0; j < 65; j++) s = fmaf(Rr[j], rel_emb[(size_t)j * DP_ + d], s);
    g_ctx[gid] += s;
}

// ---------------------------------------------------------------------------
// 11) out = ctx_perm @ Wo^T + bo   -> d_out[0 .. B*S*D)
// ---------------------------------------------------------------------------
__global__ void __launch_bounds__(256) out_kernel(const float* __restrict__ Wo,
                                                  const float* __restrict__ bo,
                                                  float* __restrict__ out) {
    const int bm = blockIdx.y * 64, bn = blockIdx.x * 64;
    gemm_tn(D_,
        [&](int r, int k) {
            int m = bm + r;
            int b = m >> 9, s = m & 511;
            int h = k >> 7, d = k & 127;
            return *(const float4*)(g_ctx + ((size_t)((b * H_ + h) * S_ + s)) * DP_ + d);
        },
        [&](int r, int k) { return *(const float4*)(Wo + (size_t)(bn + r) * D_ + k); },
        [&](int il, int jl, float v) {
            int m = bm + il, n = bn + jl;
            out[(size_t)m * D_ + n] = v + bo[n];
        });
}

// ---------------------------------------------------------------------------
// Host launcher
// ---------------------------------------------------------------------------
extern "C" void kernel_launch(void* const* d_in, const int* in_sizes, int n_in,
                              void* d_out, int out_size) {
    const float* x     = (const float*)d_in[0];
    const void*  mask  = d_in[1];
    const float* Wq    = (const float*)d_in[2];
    const float* bq    = (const float*)d_in[3];
    const float* Wk    = (const float*)d_in[4];
    const float* bk    = (const float*)d_in[5];
    const float* Wv    = (const float*)d_in[6];
    const float* bv    = (const float*)d_in[7];
    const float* Wo    = (const float*)d_in[8];
    const float* bo    = (const float*)d_in[9];
    const float* rel   = (const float*)d_in[10];
    const float* Wih_f = (const float*)d_in[11];
    const float* Whh_f = (const float*)d_in[12];
    const float* bih_f = (const float*)d_in[13];
    const float* bhh_f = (const float*)d_in[14];
    const float* Wih_b = (const float*)d_in[15];
    const float* Whh_b = (const float*)d_in[16];
    const float* bih_b = (const float*)d_in[17];
    const float* bhh_b = (const float*)d_in[18];

    float* out = (float*)d_out;
    const int attn_in_out = (out_size >= NOUT_ + BH_ * S_ * S_) ? 1 : 0;
    float* attn = attn_in_out ? (out + NOUT_) : nullptr;

    mask_norm_kernel<<<1, 1024>>>(mask);

    // QKV projections (M=4096, N=1024, K=1024) x 3
    qkv_kernel<<<dim3(D_ / 64, MS_ / 64, 3), 256>>>(x, Wq, bq, Wk, bk, Wv, bv);

    // RNN (heads 4..7 of q,k,v)
    rnn_in_kernel<<<dim3(DP_ / 64, NR_ / 64, 2), 256>>>(Wih_f, bih_f, Wih_b, bih_b);
    rnn_h1_kernel<<<(NR_ * DP_) / 256, 256>>>(bih_f, bhh_f, bhh_b);
    rnn_h2f_kernel<<<dim3(DP_ / 64, NR_ / 64), 256>>>(Whh_f, bhh_f);
    rnn_h2b_kernel<<<dim3(DP_ / 64, NR_ / 64), 256>>>(Whh_b, bih_b, bhh_b);

    // Relative-position projection P
    p_kernel<<<(ROWS_ * 65 + 255) / 256, 256>>>(rel);

    // scores -> softmax(+R) -> ctx -> +rel -> out-proj
    scores_kernel<<<dim3(S_ / 64, S_ / 64, BH_), 256>>>(attn, attn_in_out);
    softmax_kernel<<<ROWS_, 256>>>(attn, attn_in_out);
    ctx_kernel<<<dim3(DP_ / 64, S_ / 64, BH_), 256>>>(attn, attn_in_out);
    ctx_rel_kernel<<<(ROWS_ * DP_) / 256, 256>>>(rel);
    out_kernel<<<dim3(D_ / 64, MS_ / 64), 256>>>(Wo, bo, out);
}

// round 3
// speedup vs baseline: 1.6064x; 1.6064x over previous
#include <cuda_runtime.h>
#include <math.h>

// ---------------------------------------------------------------------------
// Problem constants
// ---------------------------------------------------------------------------
namespace {
constexpr int B_   = 8;
constexpr int S_   = 512;
constexpr int D_   = 1024;
constexpr int H_   = 8;
constexpr int DP_  = 128;              // head dim
constexpr int BH_  = B_ * H_;          // 64
constexpr int MS_  = B_ * S_;          // 4096  (rows of x)
constexpr int NSEG_ = 96;              // 3 streams * B * 4 heads
constexpr int NR_  = NSEG_ * S_;       // 49152 RNN rows
constexpr int ROWS_ = BH_ * S_;        // 32768 (b,h,q) rows
constexpr int NOUT_ = MS_ * D_;        // 4194304 elements of `out`
constexpr float INV_SCALE = 0.08838834764831845f;  // 1/sqrt(128)
}

// ---------------------------------------------------------------------------
// Scratch (static device globals -- no runtime allocation allowed)
// ---------------------------------------------------------------------------
__device__ float g_q  [BH_ * S_ * DP_];
__device__ float g_k  [BH_ * S_ * DP_];
__device__ float g_v  [BH_ * S_ * DP_];
__device__ float g_ctx[BH_ * S_ * DP_];
__device__ float g_A  [NR_ * DP_];   // feats @ Wih_f^T + bih_f
__device__ float g_Bm [NR_ * DP_];   // feats @ Wih_b^T + bih_b
__device__ float g_H1f[NR_ * DP_];
__device__ float g_H1b[NR_ * DP_];
__device__ float g_Yf [NR_ * DP_];
__device__ float g_P  [ROWS_ * 65];  // qs . rel_emb[j]
__device__ float g_R  [ROWS_ * 65];  // bucketed attn sums
__device__ int   g_mask[MS_];
__device__ float g_attn_fb[(size_t)BH_ * S_ * S_];  // fallback if d_out lacks attn

// ---------------------------------------------------------------------------
// 128x128x8 double-buffered SGEMM cores, 256 threads, 8x8 per thread.
//   gemm128_tn:  C = A * B^T   (A: [M,K] rm, B: [N,K] rm)
//   gemm128_nn:  C = A * B     (A: [M,K] rm, B: [K,N] rm)
// loadA(r, k) / loadB return float4 (k, col multiples of 4).
// Smem row stride 132 floats (= 528B, 16B-aligned, de-conflicts the
// transposed A/B stores while keeping float4 fragment loads legal).
// ---------------------------------------------------------------------------
#define GEMM_COMPUTE_STEP(buf)                                               \
    _Pragma("unroll")                                                        \
    for (int kk = 0; kk < 8; kk++) {                                         \
        float4 a0 = *(const float4*)&As[buf][kk][ty * 8];                    \
        float4 a1 = *(const float4*)&As[buf][kk][ty * 8 + 4];                \
        float4 b0 = *(const float4*)&Bs[buf][kk][tx * 8];                    \
        float4 b1 = *(const float4*)&Bs[buf][kk][tx * 8 + 4];                \
        float ar[8] = {a0.x, a0.y, a0.z, a0.w, a1.x, a1.y, a1.z, a1.w};      \
        float br[8] = {b0.x, b0.y, b0.z, b0.w, b1.x, b1.y, b1.z, b1.w};      \
        _Pragma("unroll")                                                    \
        for (int i = 0; i < 8; i++)                                          \
            _Pragma("unroll")                                                \
            for (int j = 0; j < 8; j++)                                      \
                acc[i][j] = fmaf(ar[i], br[j], acc[i][j]);                   \
    }

template <class FA, class FB, class FC>
__device__ __forceinline__ void gemm128_tn(int K, FA loadA, FB loadB, FC storeC) {
    __shared__ float As[2][8][132];
    __shared__ float Bs[2][8][132];
    float acc[8][8] = {};
    const int tid = threadIdx.x;
    const int lr  = tid >> 1;           // 0..127 tile row for loads
    const int lk  = (tid & 1) * 4;      // 0 or 4
    const int tx  = tid & 15;
    const int ty  = tid >> 4;

    {
        float4 a = loadA(lr, lk);
        float4 b = loadB(lr, lk);
        As[0][lk + 0][lr] = a.x; As[0][lk + 1][lr] = a.y;
        As[0][lk + 2][lr] = a.z; As[0][lk + 3][lr] = a.w;
        Bs[0][lk + 0][lr] = b.x; Bs[0][lk + 1][lr] = b.y;
        Bs[0][lk + 2][lr] = b.z; Bs[0][lk + 3][lr] = b.w;
    }
    __syncthreads();
    int buf = 0;
    for (int k0 = 8; k0 <= K; k0 += 8) {
        float4 an, bn;
        const bool more = (k0 < K);
        if (more) { an = loadA(lr, k0 + lk); bn = loadB(lr, k0 + lk); }
        GEMM_COMPUTE_STEP(buf)
        if (more) {
            int nb = buf ^ 1;
            As[nb][lk + 0][lr] = an.x; As[nb][lk + 1][lr] = an.y;
            As[nb][lk + 2][lr] = an.z; As[nb][lk + 3][lr] = an.w;
            Bs[nb][lk + 0][lr] = bn.x; Bs[nb][lk + 1][lr] = bn.y;
            Bs[nb][lk + 2][lr] = bn.z; Bs[nb][lk + 3][lr] = bn.w;
            __syncthreads();
            buf = nb;
        }
    }
#pragma unroll
    for (int i = 0; i < 8; i++)
#pragma unroll
        for (int j = 0; j < 8; j++) storeC(ty * 8 + i, tx * 8 + j, acc[i][j]);
}

template <class FA, class FB, class FC>
__device__ __forceinline__ void gemm128_nn(int K, FA loadA, FB loadB, FC storeC) {
    __shared__ float As[2][8][132];
    __shared__ float Bs[2][8][132];
    float acc[8][8] = {};
    const int tid = threadIdx.x;
    const int lr  = tid >> 1;           // A tile row
    const int lk  = (tid & 1) * 4;      // A k offset
    const int bkr = tid >> 5;           // B k row 0..7
    const int bcl = (tid & 31) * 4;     // B col 0..124
    const int tx  = tid & 15;
    const int ty  = tid >> 4;

    {
        float4 a = loadA(lr, lk);
        float4 b = loadB(bkr, bcl);
        As[0][lk + 0][lr] = a.x; As[0][lk + 1][lr] = a.y;
        As[0][lk + 2][lr] = a.z; As[0][lk + 3][lr] = a.w;
        *(float4*)&Bs[0][bkr][bcl] = b;
    }
    __syncthreads();
    int buf = 0;
    for (int k0 = 8; k0 <= K; k0 += 8) {
        float4 an, bn;
        const bool more = (k0 < K);
        if (more) { an = loadA(lr, k0 + lk); bn = loadB(k0 + bkr, bcl); }
        GEMM_COMPUTE_STEP(buf)
        if (more) {
            int nb = buf ^ 1;
            As[nb][lk + 0][lr] = an.x; As[nb][lk + 1][lr] = an.y;
            As[nb][lk + 2][lr] = an.z; As[nb][lk + 3][lr] = an.w;
            *(float4*)&Bs[nb][bkr][bcl] = bn;
            __syncthreads();
            buf = nb;
        }
    }
#pragma unroll
    for (int i = 0; i < 8; i++)
#pragma unroll
        for (int j = 0; j < 8; j++) storeC(ty * 8 + i, tx * 8 + j, acc[i][j]);
}

// ---------------------------------------------------------------------------
// 0) Mask normalization: detect uint8 / int32 / float32 encoding of the bool
//    mask and write 0/1 ints to g_mask.  Single block, deterministic.
// ---------------------------------------------------------------------------
__global__ void mask_norm_kernel(const void* raw) {
    __shared__ int f_int, f_flt;
    const unsigned int* w = (const unsigned int*)raw;
    int t = threadIdx.x;  // 1024 threads
    if (t == 0) { f_int = 1; f_flt = 1; }
    __syncthreads();
    unsigned int x = w[t];
    if (x != 0u && x != 1u) f_int = 0;
    if (x != 0u && x != 0x3F800000u) f_flt = 0;
    __syncthreads();
    if (f_int) {
        for (int i = t; i < MS_; i += 1024) g_mask[i] = (int)w[i];
    } else if (f_flt) {
        const float* f = (const float*)raw;
        for (int i = t; i < MS_; i += 1024) g_mask[i] = (f[i] != 0.f);
    } else {
        const unsigned char* bts = (const unsigned char*)raw;
        for (int i = t; i < MS_; i += 1024) g_mask[i] = (bts[i] != 0);
    }
}

// ---------------------------------------------------------------------------
// 1) QKV projections: z=0/1/2 -> q/k/v.  Epilogue: +bias, mask-zero, scatter
//    to (B,H,S,DP) head-major layout.
// ---------------------------------------------------------------------------
__global__ void __launch_bounds__(256, 2) qkv_kernel(
    const float* __restrict__ x,
    const float* __restrict__ Wq, const float* __restrict__ bq,
    const float* __restrict__ Wk, const float* __restrict__ bk,
    const float* __restrict__ Wv, const float* __restrict__ bv) {
    const int z = blockIdx.z;
    const float* W    = (z == 0) ? Wq : (z == 1) ? Wk : Wv;
    const float* bias = (z == 0) ? bq : (z == 1) ? bk : bv;
    float* out        = (z == 0) ? g_q : (z == 1) ? g_k : g_v;
    const int bm = blockIdx.y * 128, bn = blockIdx.x * 128;
    gemm128_tn(D_,
        [&](int r, int k) { return *(const float4*)(x + (size_t)(bm + r) * D_ + k); },
        [&](int r, int k) { return *(const float4*)(W + (size_t)(bn + r) * D_ + k); },
        [&](int il, int jl, float v) {
            int m = bm + il, n = bn + jl;
            int b = m >> 9, s = m & 511;
            int h = n >> 7, d = n & 127;
            float val = g_mask[m] ? 0.f : (v + bias[n]);
            out[((size_t)((b * H_ + h) * S_ + s)) * DP_ + d] = val;
        });
}

// ---------------------------------------------------------------------------
// 2) RNN input GEMMs: z=0 -> g_A = feats@Wih_f^T + bih_f
//                     z=1 -> g_Bm = feats@Wih_b^T + bih_b
// ---------------------------------------------------------------------------
__device__ __forceinline__ const float* feats_row(int rr) {
    int f = rr >> 14;             // stream: 0=q 1=k 2=v  (32*512 = 16384)
    int rem = rr & 16383;
    int bh4 = rem >> 9;           // b*4+hh
    int s   = rem & 511;
    int b = bh4 >> 2, hh = bh4 & 3;
    const float* src = (f == 0) ? g_q : (f == 1) ? g_k : g_v;
    return src + ((size_t)((b * H_ + 4 + hh) * S_ + s)) * DP_;
}

__global__ void __launch_bounds__(256, 2) rnn_in_kernel(
    const float* __restrict__ Wih_f, const float* __restrict__ bih_f,
    const float* __restrict__ Wih_b, const float* __restrict__ bih_b) {
    const int z = blockIdx.z;
    const float* W    = z ? Wih_b : Wih_f;
    const float* bias = z ? bih_b : bih_f;
    float* dst        = z ? g_Bm : g_A;
    const int bm = blockIdx.y * 128;
    gemm128_tn(DP_,
        [&](int r, int k) { return *(const float4*)(feats_row(bm + r) + k); },
        [&](int r, int k) { return *(const float4*)(W + (size_t)r * DP_ + k); },
        [&](int il, int jl, float v) {
            dst[(size_t)(bm + il) * DP_ + jl] = v + bias[jl];
        });
}

// ---------------------------------------------------------------------------
// 3) First RNN step (elementwise, shift comes for free)
// ---------------------------------------------------------------------------
__global__ void rnn_h1_kernel(const float* __restrict__ bih_f,
                              const float* __restrict__ bhh_f,
                              const float* __restrict__ bhh_b) {
    int gid = blockIdx.x * blockDim.x + threadIdx.x;
    if (gid >= NR_ * DP_) return;
    int r = gid >> 7, d = gid & 127;
    int s = r & 511;
    float af = s ? g_A[gid - DP_] : bih_f[d];
    g_H1f[gid] = tanhf(af + bhh_f[d]);
    g_H1b[gid] = tanhf(g_Bm[gid] + bhh_b[d]);
}

// ---------------------------------------------------------------------------
// 4) Forward step 2:  Yf = tanh( A + H1f@Whh_f^T + bhh_f )
// ---------------------------------------------------------------------------
__global__ void __launch_bounds__(256, 2) rnn_h2f_kernel(
    const float* __restrict__ Whh_f, const float* __restrict__ bhh_f) {
    const int bm = blockIdx.y * 128;
    gemm128_tn(DP_,
        [&](int r, int k) { return *(const float4*)(g_H1f + (size_t)(bm + r) * DP_ + k); },
        [&](int r, int k) { return *(const float4*)(Whh_f + (size_t)r * DP_ + k); },
        [&](int il, int jl, float v) {
            size_t idx = (size_t)(bm + il) * DP_ + jl;
            g_Yf[idx] = tanhf(v + g_A[idx] + bhh_f[jl]);
        });
}

// ---------------------------------------------------------------------------
// 5) Backward step 2 + combine + scatter back into q/k/v heads 4..7
// ---------------------------------------------------------------------------
__global__ void __launch_bounds__(256, 2) rnn_h2b_kernel(
    const float* __restrict__ Whh_b, const float* __restrict__ bih_b,
    const float* __restrict__ bhh_b) {
    const int bm = blockIdx.y * 128;
    gemm128_tn(DP_,
        [&](int r, int k) { return *(const float4*)(g_H1b + (size_t)(bm + r) * DP_ + k); },
        [&](int r, int k) { return *(const float4*)(Whh_b + (size_t)r * DP_ + k); },
        [&](int il, int jl, float v) {
            int m = bm + il, n = jl;
            int s = m & 511;
            float shiftB = s ? g_Bm[(size_t)(m - 1) * DP_ + n] : bih_b[n];
            float y = g_Yf[(size_t)m * DP_ + n] + tanhf(v + shiftB + bhh_b[n]);
            int f = m >> 14, rem = m & 16383, bh4 = rem >> 9;
            int b = bh4 >> 2, hh = bh4 & 3;
            float* dst = (f == 0) ? g_q : (f == 1) ? g_k : g_v;
            dst[((size_t)((b * H_ + 4 + hh) * S_ + s)) * DP_ + n] = y;
        });
}

// ---------------------------------------------------------------------------
// 6) P[row,j] = (q[row] . rel_emb[j]) / SCALE
// ---------------------------------------------------------------------------
__global__ void p_kernel(const float* __restrict__ rel_emb) {
    int gid = blockIdx.x * blockDim.x + threadIdx.x;
    if (gid >= ROWS_ * 65) return;
    int row = gid / 65, j = gid - row * 65;
    const float* qr = g_q + (size_t)row * DP_;
    const float* er = rel_emb + (size_t)j * DP_;
    float s = 0.f;
#pragma unroll 8
    for (int d = 0; d < DP_; d++) s = fmaf(qr[d], er[d], s);
    g_P[gid] = s * INV_SCALE;
}

// ---------------------------------------------------------------------------
// 7) scores (pre-softmax) into the attn buffer
// ---------------------------------------------------------------------------
__global__ void __launch_bounds__(256, 2) scores_kernel(float* __restrict__ attn,
                                                        int attn_in_out) {
    float* ap = attn_in_out ? attn : g_attn_fb;
    const int z = blockIdx.z;              // bh
    const int b = z >> 3;
    const int bm = blockIdx.y * 128, bn = blockIdx.x * 128;
    const float* qb = g_q + (size_t)z * S_ * DP_;
    const float* kb = g_k + (size_t)z * S_ * DP_;
    gemm128_tn(DP_,
        [&](int r, int k) { return *(const float4*)(qb + (size_t)(bm + r) * DP_ + k); },
        [&](int r, int k) { return *(const float4*)(kb + (size_t)(bn + r) * DP_ + k); },
        [&](int il, int jl, float v) {
            int qi = bm + il, ki = bn + jl;
            float val;
            if (g_mask[b * S_ + ki]) {
                val = -1e18f;
            } else {
                int off = ki - qi;
                off = off < -32 ? -32 : (off > 32 ? 32 : off);
                val = v * INV_SCALE + g_P[((size_t)z * S_ + qi) * 65 + off + 32];
            }
            ap[(size_t)z * S_ * S_ + (size_t)qi * S_ + ki] = val;
        });
}

// ---------------------------------------------------------------------------
// 8) Softmax per row + bucketed rel sums R.  One block (256 thr) per row.
// ---------------------------------------------------------------------------
__device__ __forceinline__ float blk_reduce(float v, float* red, bool is_max) {
#pragma unroll
    for (int o = 16; o > 0; o >>= 1) {
        float w = __shfl_xor_sync(0xffffffffu, v, o);
        v = is_max ? fmaxf(v, w) : (v + w);
    }
    int warp = threadIdx.x >> 5, lane = threadIdx.x & 31;
    if (lane == 0) red[warp] = v;
    __syncthreads();
    float r = red[0];
#pragma unroll
    for (int i = 1; i < 8; i++) r = is_max ? fmaxf(r, red[i]) : (r + red[i]);
    __syncthreads();
    return r;
}

__global__ void __launch_bounds__(256) softmax_kernel(float* __restrict__ attn,
                                                      int attn_in_out) {
    float* ap = attn_in_out ? attn : g_attn_fb;
    int row = blockIdx.x;                 // bh*S + q
    int q = row & 511;
    float* p = ap + (size_t)row * S_;
    __shared__ float sh[S_];
    __shared__ float red[8];
    int t = threadIdx.x;
    float v0 = p[t], v1 = p[t + 256];
    float mx = blk_reduce(fmaxf(v0, v1), red, true);
    float e0 = expf(v0 - mx), e1 = expf(v1 - mx);
    float sum = blk_reduce(e0 + e1, red, false);
    float inv = 1.f / sum;
    e0 *= inv; e1 *= inv;
    p[t] = e0; p[t + 256] = e1;
    sh[t] = e0; sh[t + 256] = e1;
    float r0 = 0.f, r64 = 0.f;
    if (t <= q - 32)        r0  += e0;
    if (t >= q + 32)        r64 += e0;
    if (t + 256 <= q - 32)  r0  += e1;
    if (t + 256 >= q + 32)  r64 += e1;
    r0  = blk_reduce(r0,  red, false);
    r64 = blk_reduce(r64, red, false);
    float* Rr = g_R + (size_t)row * 65;
    if (t == 0) { Rr[0] = r0; Rr[64] = r64; }
    if (t >= 1 && t <= 63) {
        int k = q + t - 32;
        Rr[t] = (k >= 0 && k < S_) ? sh[k] : 0.f;
    }
}

// ---------------------------------------------------------------------------
// 9) ctx = attn @ v  (NN GEMM, per bh)
// ---------------------------------------------------------------------------
__global__ void __launch_bounds__(256, 2) ctx_kernel(const float* __restrict__ attn,
                                                     int attn_in_out) {
    const float* ap = attn_in_out ? attn : g_attn_fb;
    const int z = blockIdx.z;
    const int bm = blockIdx.y * 128;
    const float* Ab = ap + (size_t)z * S_ * S_;
    const float* Vb = g_v + (size_t)z * S_ * DP_;
    gemm128_nn(S_,
        [&](int r, int k) { return *(const float4*)(Ab + (size_t)(bm + r) * S_ + k); },
        [&](int k, int n) { return *(const float4*)(Vb + (size_t)k * DP_ + n); },
        [&](int il, int jl, float v) {
            g_ctx[(size_t)z * S_ * DP_ + (size_t)(bm + il) * DP_ + jl] = v;
        });
}

// ---------------------------------------------------------------------------
// 10) ctx += R @ rel_emb   (K=65, tiny)
// ---------------------------------------------------------------------------
__global__ void ctx_rel_kernel(const float* __restrict__ rel_emb) {
    int gid = blockIdx.x * blockDim.x + threadIdx.x;
    if (gid >= ROWS_ * DP_) return;
    int row = gid >> 7, d = gid & 127;
    const float* Rr = g_R + (size_t)row * 65;
    float s = 0.f;
#pragma unroll
    for (int j = 0; j < 65; j++) s = fmaf(Rr[j], rel_emb[(size_t)j * DP_ + d], s);
    g_ctx[gid] += s;
}

// ---------------------------------------------------------------------------
// 11) out = ctx_perm @ Wo^T + bo   -> d_out[0 .. B*S*D)
// ---------------------------------------------------------------------------
__global__ void __launch_bounds__(256, 2) out_kernel(const float* __restrict__ Wo,
                                                     const float* __restrict__ bo,
                                                     float* __restrict__ out) {
    const int bm = blockIdx.y * 128, bn = blockIdx.x * 128;
    gemm128_tn(D_,
        [&](int r, int k) {
            int m = bm + r;
            int b = m >> 9, s = m & 511;
            int h = k >> 7, d = k & 127;
            return *(const float4*)(g_ctx + ((size_t)((b * H_ + h) * S_ + s)) * DP_ + d);
        },
        [&](int r, int k) { return *(const float4*)(Wo + (size_t)(bn + r) * D_ + k); },
        [&](int il, int jl, float v) {
            int m = bm + il, n = bn + jl;
            out[(size_t)m * D_ + n] = v + bo[n];
        });
}

// ---------------------------------------------------------------------------
// Host launcher
// ---------------------------------------------------------------------------
extern "C" void kernel_launch(void* const* d_in, const int* in_sizes, int n_in,
                              void* d_out, int out_size) {
    const float* x     = (const float*)d_in[0];
    const void*  mask  = d_in[1];
    const float* Wq    = (const float*)d_in[2];
    const float* bq    = (const float*)d_in[3];
    const float* Wk    = (const float*)d_in[4];
    const float* bk    = (const float*)d_in[5];
    const float* Wv    = (const float*)d_in[6];
    const float* bv    = (const float*)d_in[7];
    const float* Wo    = (const float*)d_in[8];
    const float* bo    = (const float*)d_in[9];
    const float* rel   = (const float*)d_in[10];
    const float* Wih_f = (const float*)d_in[11];
    const float* Whh_f = (const float*)d_in[12];
    const float* bih_f = (const float*)d_in[13];
    const float* bhh_f = (const float*)d_in[14];
    const float* Wih_b = (const float*)d_in[15];
    const float* Whh_b = (const float*)d_in[16];
    const float* bih_b = (const float*)d_in[17];
    const float* bhh_b = (const float*)d_in[18];

    float* out = (float*)d_out;
    const int attn_in_out = (out_size >= NOUT_ + BH_ * S_ * S_) ? 1 : 0;
    float* attn = attn_in_out ? (out + NOUT_) : nullptr;

    mask_norm_kernel<<<1, 1024>>>(mask);

    // QKV projections (M=4096, N=1024, K=1024) x 3
    qkv_kernel<<<dim3(D_ / 128, MS_ / 128, 3), 256>>>(x, Wq, bq, Wk, bk, Wv, bv);

    // RNN (heads 4..7 of q,k,v)
    rnn_in_kernel<<<dim3(1, NR_ / 128, 2), 256>>>(Wih_f, bih_f, Wih_b, bih_b);
    rnn_h1_kernel<<<(NR_ * DP_) / 256, 256>>>(bih_f, bhh_f, bhh_b);
    rnn_h2f_kernel<<<dim3(1, NR_ / 128), 256>>>(Whh_f, bhh_f);
    rnn_h2b_kernel<<<dim3(1, NR_ / 128), 256>>>(Whh_b, bih_b, bhh_b);

    // Relative-position projection P
    p_kernel<<<(ROWS_ * 65 + 255) / 256, 256>>>(rel);

    // scores -> softmax(+R) -> ctx -> +rel -> out-proj
    scores_kernel<<<dim3(S_ / 128, S_ / 128, BH_), 256>>>(attn, attn_in_out);
    softmax_kernel<<<ROWS_, 256>>>(attn, attn_in_out);
    ctx_kernel<<<dim3(1, S_ / 128, BH_), 256>>>(attn, attn_in_out);
    ctx_rel_kernel<<<(ROWS_ * DP_) / 256, 256>>>(rel);
    out_kernel<<<dim3(D_ / 128, MS_ / 128), 256>>>(Wo, bo, out);
}

// round 4
// speedup vs baseline: 2.2379x; 1.3931x over previous
#include <cuda_runtime.h>
#include <math.h>

// ---------------------------------------------------------------------------
// Problem constants
// ---------------------------------------------------------------------------
namespace {
constexpr int B_   = 8;
constexpr int S_   = 512;
constexpr int D_   = 1024;
constexpr int H_   = 8;
constexpr int DP_  = 128;              // head dim
constexpr int BH_  = B_ * H_;          // 64
constexpr int MS_  = B_ * S_;          // 4096  (rows of x)
constexpr int NR_  = 96 * S_;          // 49152 RNN rows
constexpr int ROWS_ = BH_ * S_;        // 32768 (b,h,q) rows
constexpr int NOUT_ = MS_ * D_;        // 4194304 elements of `out`
constexpr float INV_SCALE = 0.08838834764831845f;  // 1/sqrt(128)
constexpr int KS  = 16;                // k per smem stage
constexpr int LDSW = 132;              // smem row stride (words)
}

// ---------------------------------------------------------------------------
// Scratch (static device globals -- no runtime allocation allowed)
// ---------------------------------------------------------------------------
__device__ float g_q  [BH_ * S_ * DP_];
__device__ float g_k  [BH_ * S_ * DP_];
__device__ float g_v  [BH_ * S_ * DP_];
__device__ float g_ctx[BH_ * S_ * DP_];
__device__ float g_A  [NR_ * DP_];
__device__ float g_Bm [NR_ * DP_];
__device__ float g_H1f[NR_ * DP_];
__device__ float g_H1b[NR_ * DP_];
__device__ float g_Yf [NR_ * DP_];
__device__ float g_P  [ROWS_ * 65];
__device__ float g_R  [ROWS_ * 65];
__device__ int   g_mask[MS_];
__device__ float g_attn_fb[(size_t)BH_ * S_ * S_];

// ---------------------------------------------------------------------------
// tf32 helpers
// ---------------------------------------------------------------------------
__device__ __forceinline__ unsigned f2tf(float x) {
    unsigned r;
    asm("cvt.rna.tf32.f32 %0, %1;" : "=r"(r) : "f"(x));
    return r;
}

__device__ __forceinline__ void mma_tf32(float* d, const unsigned* a, const unsigned* b) {
    asm volatile(
        "mma.sync.aligned.m16n8k8.row.col.f32.tf32.tf32.f32 "
        "{%0,%1,%2,%3}, {%4,%5,%6,%7}, {%8,%9}, {%0,%1,%2,%3};\n"
        : "+f"(d[0]), "+f"(d[1]), "+f"(d[2]), "+f"(d[3])
        : "r"(a[0]), "r"(a[1]), "r"(a[2]), "r"(a[3]), "r"(b[0]), "r"(b[1]));
}

// ---------------------------------------------------------------------------
// 128x128 tf32-MMA GEMM cores. 256 threads = 8 warps (2x4), warp tile 64x32.
// Smem layout [k][x] (k-major) stride 132 -> conflict-free fragment loads.
//   mm128_tn:  C = A * B^T   (A: [M,K] rm, B: [N,K] rm)
//   mm128_nn:  C = A * B     (A: [M,K] rm, B: [K,N] rm)
// ---------------------------------------------------------------------------
#define MM_COMPUTE(buf)                                                       \
    _Pragma("unroll")                                                         \
    for (int kc = 0; kc < KS; kc += 8) {                                      \
        unsigned af[4][4], bf[4][2];                                          \
        _Pragma("unroll")                                                     \
        for (int i = 0; i < 4; i++) {                                         \
            int m = wm + 16 * i;                                              \
            af[i][0] = As[buf][kc + la3][m + lg];                             \
            af[i][1] = As[buf][kc + la3][m + 8 + lg];                         \
            af[i][2] = As[buf][kc + 4 + la3][m + lg];                         \
            af[i][3] = As[buf][kc + 4 + la3][m + 8 + lg];                     \
        }                                                                     \
        _Pragma("unroll")                                                     \
        for (int j = 0; j < 4; j++) {                                         \
            int n = wn + 8 * j;                                               \
            bf[j][0] = Bs[buf][kc + la3][n + lg];                             \
            bf[j][1] = Bs[buf][kc + 4 + la3][n + lg];                         \
        }                                                                     \
        _Pragma("unroll")                                                     \
        for (int i = 0; i < 4; i++)                                           \
            _Pragma("unroll")                                                 \
            for (int j = 0; j < 4; j++) mma_tf32(acc[i][j], af[i], bf[j]);    \
    }

#define MM_EPILOGUE                                                           \
    _Pragma("unroll")                                                         \
    for (int i = 0; i < 4; i++)                                               \
        _Pragma("unroll")                                                     \
        for (int j = 0; j < 4; j++) {                                         \
            int r0 = wm + 16 * i + lg, c0 = wn + 8 * j + 2 * la3;             \
            storeC(r0,     c0,     acc[i][j][0]);                             \
            storeC(r0,     c0 + 1, acc[i][j][1]);                             \
            storeC(r0 + 8, c0,     acc[i][j][2]);                             \
            storeC(r0 + 8, c0 + 1, acc[i][j][3]);                             \
        }

template <class FA, class FB, class FC>
__device__ __forceinline__ void mm128_tn(int K, FA loadA, FB loadB, FC storeC) {
    __shared__ unsigned As[2][KS][LDSW];
    __shared__ unsigned Bs[2][KS][LDSW];
    float acc[4][4][4] = {};
    const int tid  = threadIdx.x;
    const int lane = tid & 31;
    const int warp = tid >> 5;
    const int la3  = lane & 3, lg = lane >> 2;
    const int wm   = (warp & 1) * 64, wn = (warp >> 1) * 32;
    const int lr   = tid >> 1;           // 0..127 tile row
    const int lk   = (tid & 1) * 8;      // 0 or 8

    float4 ra0 = loadA(lr, lk), ra1 = loadA(lr, lk + 4);
    float4 rb0 = loadB(lr, lk), rb1 = loadB(lr, lk + 4);
#define MM_TN_STORE(nb)                                                        \
    As[nb][lk+0][lr]=f2tf(ra0.x); As[nb][lk+1][lr]=f2tf(ra0.y);                \
    As[nb][lk+2][lr]=f2tf(ra0.z); As[nb][lk+3][lr]=f2tf(ra0.w);                \
    As[nb][lk+4][lr]=f2tf(ra1.x); As[nb][lk+5][lr]=f2tf(ra1.y);                \
    As[nb][lk+6][lr]=f2tf(ra1.z); As[nb][lk+7][lr]=f2tf(ra1.w);                \
    Bs[nb][lk+0][lr]=f2tf(rb0.x); Bs[nb][lk+1][lr]=f2tf(rb0.y);                \
    Bs[nb][lk+2][lr]=f2tf(rb0.z); Bs[nb][lk+3][lr]=f2tf(rb0.w);                \
    Bs[nb][lk+4][lr]=f2tf(rb1.x); Bs[nb][lk+5][lr]=f2tf(rb1.y);                \
    Bs[nb][lk+6][lr]=f2tf(rb1.z); Bs[nb][lk+7][lr]=f2tf(rb1.w);
    MM_TN_STORE(0)
    __syncthreads();
    int buf = 0;
    for (int k0 = KS; k0 <= K; k0 += KS) {
        const bool more = (k0 < K);
        if (more) {
            ra0 = loadA(lr, k0 + lk); ra1 = loadA(lr, k0 + lk + 4);
            rb0 = loadB(lr, k0 + lk); rb1 = loadB(lr, k0 + lk + 4);
        }
        MM_COMPUTE(buf)
        if (more) {
            int nb = buf ^ 1;
            MM_TN_STORE(nb)
            __syncthreads();
            buf = nb;
        }
    }
    MM_EPILOGUE
#undef MM_TN_STORE
}

template <class FA, class FB, class FC>
__device__ __forceinline__ void mm128_nn(int K, FA loadA, FB loadB, FC storeC) {
    __shared__ unsigned As[2][KS][LDSW];
    __shared__ unsigned Bs[2][KS][LDSW];
    float acc[4][4][4] = {};
    const int tid  = threadIdx.x;
    const int lane = tid & 31;
    const int warp = tid >> 5;
    const int la3  = lane & 3, lg = lane >> 2;
    const int wm   = (warp & 1) * 64, wn = (warp >> 1) * 32;
    const int lr   = tid >> 1;           // A tile row
    const int lk   = (tid & 1) * 8;      // A k offset
    const int bkr  = tid >> 4;           // B k row 0..15
    const int bcl  = (tid & 15) * 8;     // B col 0..120

    float4 ra0 = loadA(lr, lk), ra1 = loadA(lr, lk + 4);
    float4 rb0 = loadB(bkr, bcl), rb1 = loadB(bkr, bcl + 4);
#define MM_NN_STORE(nb)                                                        \
    As[nb][lk+0][lr]=f2tf(ra0.x); As[nb][lk+1][lr]=f2tf(ra0.y);                \
    As[nb][lk+2][lr]=f2tf(ra0.z); As[nb][lk+3][lr]=f2tf(ra0.w);                \
    As[nb][lk+4][lr]=f2tf(ra1.x); As[nb][lk+5][lr]=f2tf(ra1.y);                \
    As[nb][lk+6][lr]=f2tf(ra1.z); As[nb][lk+7][lr]=f2tf(ra1.w);                \
    Bs[nb][bkr][bcl+0]=f2tf(rb0.x); Bs[nb][bkr][bcl+1]=f2tf(rb0.y);            \
    Bs[nb][bkr][bcl+2]=f2tf(rb0.z); Bs[nb][bkr][bcl+3]=f2tf(rb0.w);            \
    Bs[nb][bkr][bcl+4]=f2tf(rb1.x); Bs[nb][bkr][bcl+5]=f2tf(rb1.y);            \
    Bs[nb][bkr][bcl+6]=f2tf(rb1.z); Bs[nb][bkr][bcl+7]=f2tf(rb1.w);
    MM_NN_STORE(0)
    __syncthreads();
    int buf = 0;
    for (int k0 = KS; k0 <= K; k0 += KS) {
        const bool more = (k0 < K);
        if (more) {
            ra0 = loadA(lr, k0 + lk); ra1 = loadA(lr, k0 + lk + 4);
            rb0 = loadB(k0 + bkr, bcl); rb1 = loadB(k0 + bkr, bcl + 4);
        }
        MM_COMPUTE(buf)
        if (more) {
            int nb = buf ^ 1;
            MM_NN_STORE(nb)
            __syncthreads();
            buf = nb;
        }
    }
    MM_EPILOGUE
#undef MM_NN_STORE
}

// ---------------------------------------------------------------------------
// 0) Mask normalization (detect uint8 / int32 / float32 encodings)
// ---------------------------------------------------------------------------
__global__ void mask_norm_kernel(const void* raw) {
    __shared__ int f_int, f_flt;
    const unsigned int* w = (const unsigned int*)raw;
    int t = threadIdx.x;  // 1024 threads
    if (t == 0) { f_int = 1; f_flt = 1; }
    __syncthreads();
    unsigned int x = w[t];
    if (x != 0u && x != 1u) f_int = 0;
    if (x != 0u && x != 0x3F800000u) f_flt = 0;
    __syncthreads();
    if (f_int) {
        for (int i = t; i < MS_; i += 1024) g_mask[i] = (int)w[i];
    } else if (f_flt) {
        const float* f = (const float*)raw;
        for (int i = t; i < MS_; i += 1024) g_mask[i] = (f[i] != 0.f);
    } else {
        const unsigned char* bts = (const unsigned char*)raw;
        for (int i = t; i < MS_; i += 1024) g_mask[i] = (bts[i] != 0);
    }
}

// ---------------------------------------------------------------------------
// 1) QKV projections (MMA) + bias + mask-zero + head-major scatter
// ---------------------------------------------------------------------------
__global__ void __launch_bounds__(256, 2) qkv_kernel(
    const float* __restrict__ x,
    const float* __restrict__ Wq, const float* __restrict__ bq,
    const float* __restrict__ Wk, const float* __restrict__ bk,
    const float* __restrict__ Wv, const float* __restrict__ bv) {
    const int z = blockIdx.z;
    const float* W    = (z == 0) ? Wq : (z == 1) ? Wk : Wv;
    const float* bias = (z == 0) ? bq : (z == 1) ? bk : bv;
    float* out        = (z == 0) ? g_q : (z == 1) ? g_k : g_v;
    const int bm = blockIdx.y * 128, bn = blockIdx.x * 128;
    mm128_tn(D_,
        [&](int r, int k) { return *(const float4*)(x + (size_t)(bm + r) * D_ + k); },
        [&](int r, int k) { return *(const float4*)(W + (size_t)(bn + r) * D_ + k); },
        [&](int il, int jl, float v) {
            int m = bm + il, n = bn + jl;
            int b = m >> 9, s = m & 511;
            int h = n >> 7, d = n & 127;
            float val = g_mask[m] ? 0.f : (v + bias[n]);
            out[((size_t)((b * H_ + h) * S_ + s)) * DP_ + d] = val;
        });
}

// ---------------------------------------------------------------------------
// 2) RNN input GEMMs
// ---------------------------------------------------------------------------
__device__ __forceinline__ const float* feats_row(int rr) {
    int f = rr >> 14;
    int rem = rr & 16383;
    int bh4 = rem >> 9;
    int s   = rem & 511;
    int b = bh4 >> 2, hh = bh4 & 3;
    const float* src = (f == 0) ? g_q : (f == 1) ? g_k : g_v;
    return src + ((size_t)((b * H_ + 4 + hh) * S_ + s)) * DP_;
}

__global__ void __launch_bounds__(256, 2) rnn_in_kernel(
    const float* __restrict__ Wih_f, const float* __restrict__ bih_f,
    const float* __restrict__ Wih_b, const float* __restrict__ bih_b) {
    const int z = blockIdx.z;
    const float* W    = z ? Wih_b : Wih_f;
    const float* bias = z ? bih_b : bih_f;
    float* dst        = z ? g_Bm : g_A;
    const int bm = blockIdx.y * 128;
    mm128_tn(DP_,
        [&](int r, int k) { return *(const float4*)(feats_row(bm + r) + k); },
        [&](int r, int k) { return *(const float4*)(W + (size_t)r * DP_ + k); },
        [&](int il, int jl, float v) {
            dst[(size_t)(bm + il) * DP_ + jl] = v + bias[jl];
        });
}

// ---------------------------------------------------------------------------
// 3) First RNN step (elementwise)
// ---------------------------------------------------------------------------
__global__ void rnn_h1_kernel(const float* __restrict__ bih_f,
                              const float* __restrict__ bhh_f,
                              const float* __restrict__ bhh_b) {
    int gid = blockIdx.x * blockDim.x + threadIdx.x;
    if (gid >= NR_ * DP_) return;
    int r = gid >> 7, d = gid & 127;
    int s = r & 511;
    float af = s ? g_A[gid - DP_] : bih_f[d];
    g_H1f[gid] = tanhf(af + bhh_f[d]);
    g_H1b[gid] = tanhf(g_Bm[gid] + bhh_b[d]);
}

// ---------------------------------------------------------------------------
// 4) Forward step 2:  Yf = tanh( A + H1f@Whh_f^T + bhh_f )
// ---------------------------------------------------------------------------
__global__ void __launch_bounds__(256, 2) rnn_h2f_kernel(
    const float* __restrict__ Whh_f, const float* __restrict__ bhh_f) {
    const int bm = blockIdx.y * 128;
    mm128_tn(DP_,
        [&](int r, int k) { return *(const float4*)(g_H1f + (size_t)(bm + r) * DP_ + k); },
        [&](int r, int k) { return *(const float4*)(Whh_f + (size_t)r * DP_ + k); },
        [&](int il, int jl, float v) {
            size_t idx = (size_t)(bm + il) * DP_ + jl;
            g_Yf[idx] = tanhf(v + g_A[idx] + bhh_f[jl]);
        });
}

// ---------------------------------------------------------------------------
// 5) Backward step 2 + combine + scatter back into q/k/v heads 4..7
// ---------------------------------------------------------------------------
__global__ void __launch_bounds__(256, 2) rnn_h2b_kernel(
    const float* __restrict__ Whh_b, const float* __restrict__ bih_b,
    const float* __restrict__ bhh_b) {
    const int bm = blockIdx.y * 128;
    mm128_tn(DP_,
        [&](int r, int k) { return *(const float4*)(g_H1b + (size_t)(bm + r) * DP_ + k); },
        [&](int r, int k) { return *(const float4*)(Whh_b + (size_t)r * DP_ + k); },
        [&](int il, int jl, float v) {
            int m = bm + il, n = jl;
            int s = m & 511;
            float shiftB = s ? g_Bm[(size_t)(m - 1) * DP_ + n] : bih_b[n];
            float y = g_Yf[(size_t)m * DP_ + n] + tanhf(v + shiftB + bhh_b[n]);
            int f = m >> 14, rem = m & 16383, bh4 = rem >> 9;
            int b = bh4 >> 2, hh = bh4 & 3;
            float* dst = (f == 0) ? g_q : (f == 1) ? g_k : g_v;
            dst[((size_t)((b * H_ + 4 + hh) * S_ + s)) * DP_ + n] = y;
        });
}

// ---------------------------------------------------------------------------
// 6) P[row,j] = (q[row] . rel_emb[j]) / SCALE
// ---------------------------------------------------------------------------
__global__ void p_kernel(const float* __restrict__ rel_emb) {
    int gid = blockIdx.x * blockDim.x + threadIdx.x;
    if (gid >= ROWS_ * 65) return;
    int row = gid / 65, j = gid - row * 65;
    const float* qr = g_q + (size_t)row * DP_;
    const float* er = rel_emb + (size_t)j * DP_;
    float s = 0.f;
#pragma unroll 8
    for (int d = 0; d < DP_; d++) s = fmaf(qr[d], er[d], s);
    g_P[gid] = s * INV_SCALE;
}

// ---------------------------------------------------------------------------
// 7) scores (pre-softmax) into the attn buffer
// ---------------------------------------------------------------------------
__global__ void __launch_bounds__(256, 2) scores_kernel(float* __restrict__ attn,
                                                        int attn_in_out) {
    float* ap = attn_in_out ? attn : g_attn_fb;
    const int z = blockIdx.z;
    const int b = z >> 3;
    const int bm = blockIdx.y * 128, bn = blockIdx.x * 128;
    const float* qb = g_q + (size_t)z * S_ * DP_;
    const float* kb = g_k + (size_t)z * S_ * DP_;
    mm128_tn(DP_,
        [&](int r, int k) { return *(const float4*)(qb + (size_t)(bm + r) * DP_ + k); },
        [&](int r, int k) { return *(const float4*)(kb + (size_t)(bn + r) * DP_ + k); },
        [&](int il, int jl, float v) {
            int qi = bm + il, ki = bn + jl;
            float val;
            if (g_mask[b * S_ + ki]) {
                val = -1e18f;
            } else {
                int off = ki - qi;
                off = off < -32 ? -32 : (off > 32 ? 32 : off);
                val = v * INV_SCALE + g_P[((size_t)z * S_ + qi) * 65 + off + 32];
            }
            ap[(size_t)z * S_ * S_ + (size_t)qi * S_ + ki] = val;
        });
}

// ---------------------------------------------------------------------------
// 8) Softmax per row + bucketed rel sums R
// ---------------------------------------------------------------------------
__device__ __forceinline__ float blk_reduce(float v, float* red, bool is_max) {
#pragma unroll
    for (int o = 16; o > 0; o >>= 1) {
        float w = __shfl_xor_sync(0xffffffffu, v, o);
        v = is_max ? fmaxf(v, w) : (v + w);
    }
    int warp = threadIdx.x >> 5, lane = threadIdx.x & 31;
    if (lane == 0) red[warp] = v;
    __syncthreads();
    float r = red[0];
#pragma unroll
    for (int i = 1; i < 8; i++) r = is_max ? fmaxf(r, red[i]) : (r + red[i]);
    __syncthreads();
    return r;
}

__global__ void __launch_bounds__(256) softmax_kernel(float* __restrict__ attn,
                                                      int attn_in_out) {
    float* ap = attn_in_out ? attn : g_attn_fb;
    int row = blockIdx.x;
    int q = row & 511;
    float* p = ap + (size_t)row * S_;
    __shared__ float sh[S_];
    __shared__ float red[8];
    int t = threadIdx.x;
    float v0 = p[t], v1 = p[t + 256];
    float mx = blk_reduce(fmaxf(v0, v1), red, true);
    float e0 = expf(v0 - mx), e1 = expf(v1 - mx);
    float sum = blk_reduce(e0 + e1, red, false);
    float inv = 1.f / sum;
    e0 *= inv; e1 *= inv;
    p[t] = e0; p[t + 256] = e1;
    sh[t] = e0; sh[t + 256] = e1;
    float r0 = 0.f, r64 = 0.f;
    if (t <= q - 32)        r0  += e0;
    if (t >= q + 32)        r64 += e0;
    if (t + 256 <= q - 32)  r0  += e1;
    if (t + 256 >= q + 32)  r64 += e1;
    r0  = blk_reduce(r0,  red, false);
    r64 = blk_reduce(r64, red, false);
    float* Rr = g_R + (size_t)row * 65;
    if (t == 0) { Rr[0] = r0; Rr[64] = r64; }
    if (t >= 1 && t <= 63) {
        int k = q + t - 32;
        Rr[t] = (k >= 0 && k < S_) ? sh[k] : 0.f;
    }
}

// ---------------------------------------------------------------------------
// 9) ctx = attn @ v  (NN MMA, per bh)
// ---------------------------------------------------------------------------
__global__ void __launch_bounds__(256, 2) ctx_kernel(const float* __restrict__ attn,
                                                     int attn_in_out) {
    const float* ap = attn_in_out ? attn : g_attn_fb;
    const int z = blockIdx.z;
    const int bm = blockIdx.y * 128;
    const float* Ab = ap + (size_t)z * S_ * S_;
    const float* Vb = g_v + (size_t)z * S_ * DP_;
    mm128_nn(S_,
        [&](int r, int k) { return *(const float4*)(Ab + (size_t)(bm + r) * S_ + k); },
        [&](int k, int n) { return *(const float4*)(Vb + (size_t)k * DP_ + n); },
        [&](int il, int jl, float v) {
            g_ctx[(size_t)z * S_ * DP_ + (size_t)(bm + il) * DP_ + jl] = v;
        });
}

// ---------------------------------------------------------------------------
// 10) ctx += R @ rel_emb
// ---------------------------------------------------------------------------
__global__ void ctx_rel_kernel(const float* __restrict__ rel_emb) {
    int gid = blockIdx.x * blockDim.x + threadIdx.x;
    if (gid >= ROWS_ * DP_) return;
    int row = gid >> 7, d = gid & 127;
    const float* Rr = g_R + (size_t)row * 65;
    float s = 0.f;
#pragma unroll
    for (int j = 0; j < 65; j++) s = fmaf(Rr[j], rel_emb[(size_t)j * DP_ + d], s);
    g_ctx[gid] += s;
}

// ---------------------------------------------------------------------------
// 11) out = ctx_perm @ Wo^T + bo
// ---------------------------------------------------------------------------
__global__ void __launch_bounds__(256, 2) out_kernel(const float* __restrict__ Wo,
                                                     const float* __restrict__ bo,
                                                     float* __restrict__ out) {
    const int bm = blockIdx.y * 128, bn = blockIdx.x * 128;
    mm128_tn(D_,
        [&](int r, int k) {
            int m = bm + r;
            int b = m >> 9, s = m & 511;
            int h = k >> 7, d = k & 127;
            return *(const float4*)(g_ctx + ((size_t)((b * H_ + h) * S_ + s)) * DP_ + d);
        },
        [&](int r, int k) { return *(const float4*)(Wo + (size_t)(bn + r) * D_ + k); },
        [&](int il, int jl, float v) {
            int m = bm + il, n = bn + jl;
            out[(size_t)m * D_ + n] = v + bo[n];
        });
}

// ---------------------------------------------------------------------------
// Host launcher
// ---------------------------------------------------------------------------
extern "C" void kernel_launch(void* const* d_in, const int* in_sizes, int n_in,
                              void* d_out, int out_size) {
    const float* x     = (const float*)d_in[0];
    const void*  mask  = d_in[1];
    const float* Wq    = (const float*)d_in[2];
    const float* bq    = (const float*)d_in[3];
    const float* Wk    = (const float*)d_in[4];
    const float* bk    = (const float*)d_in[5];
    const float* Wv    = (const float*)d_in[6];
    const float* bv    = (const float*)d_in[7];
    const float* Wo    = (const float*)d_in[8];
    const float* bo    = (const float*)d_in[9];
    const float* rel   = (const float*)d_in[10];
    const float* Wih_f = (const float*)d_in[11];
    const float* Whh_f = (const float*)d_in[12];
    const float* bih_f = (const float*)d_in[13];
    const float* bhh_f = (const float*)d_in[14];
    const float* Wih_b = (const float*)d_in[15];
    const float* Whh_b = (const float*)d_in[16];
    const float* bih_b = (const float*)d_in[17];
    const float* bhh_b = (const float*)d_in[18];

    float* out = (float*)d_out;
    const int attn_in_out = (out_size >= NOUT_ + BH_ * S_ * S_) ? 1 : 0;
    float* attn = attn_in_out ? (out + NOUT_) : nullptr;

    mask_norm_kernel<<<1, 1024>>>(mask);

    qkv_kernel<<<dim3(D_ / 128, MS_ / 128, 3), 256>>>(x, Wq, bq, Wk, bk, Wv, bv);

    rnn_in_kernel<<<dim3(1, NR_ / 128, 2), 256>>>(Wih_f, bih_f, Wih_b, bih_b);
    rnn_h1_kernel<<<(NR_ * DP_) / 256, 256>>>(bih_f, bhh_f, bhh_b);
    rnn_h2f_kernel<<<dim3(1, NR_ / 128), 256>>>(Whh_f, bhh_f);
    rnn_h2b_kernel<<<dim3(1, NR_ / 128), 256>>>(Whh_b, bih_b, bhh_b);

    p_kernel<<<(ROWS_ * 65 + 255) / 256, 256>>>(rel);

    scores_kernel<<<dim3(S_ / 128, S_ / 128, BH_), 256>>>(attn, attn_in_out);
    softmax_kernel<<<ROWS_, 256>>>(attn, attn_in_out);
    ctx_kernel<<<dim3(1, S_ / 128, BH_), 256>>>(attn, attn_in_out);
    ctx_rel_kernel<<<(ROWS_ * DP_) / 256, 256>>>(rel);
    out_kernel<<<dim3(D_ / 128, MS_ / 128), 256>>>(Wo, bo, out);
}